// round 7
// baseline (speedup 1.0000x reference)
#include <cuda_runtime.h>
#include <math.h>

// Problem constants (fixed by the dataset)
#define NN 8192          // atoms
#define NB 32            // graphs
#define NH 64            // hidden
#define NK 729           // 9^3 lattice points (k=0 kept with w=0)

#define TWO_PI  6.28318530717958647692f
#define FOUR_PI 12.5663706143591729539f

// -------- device scratch (no allocations allowed) --------
__device__ float g_inv[NB][9];      // inverse cells, row-major [d][h]
__device__ float g_vinv[NB];        // 1 / max(|det|, 1e-6)
__device__ int   g_off[NB + 1];     // batch segment offsets (batch is sorted)
__device__ float g_w[NB][NK];       // per-(graph,k) radial weight
// per-atom phasor table: row = (d*9 + (m+4))*2 + {re,im}, col = atom (coalesced)
__device__ float g_phas[54][NN];

// ---------------------------------------------------------------------------
// Kernel 0: 3x3 inverses (double precision) + volumes + batch offsets
// ---------------------------------------------------------------------------
__global__ void k_setup(const float* __restrict__ cell, const int* __restrict__ batch)
{
    int t = threadIdx.x;
    if (t < NB) {
        const float* c = cell + t * 9;
        double a = c[0], b = c[1], cc = c[2];
        double d = c[3], e = c[4], f  = c[5];
        double g = c[6], h = c[7], i  = c[8];
        double A  = e * i - f * h;
        double Bv = f * g - d * i;
        double C  = d * h - e * g;
        double det = a * A + b * Bv + cc * C;
        double vol = fabs(det);
        if (vol < 1e-6) vol = 1e-6;
        g_vinv[t] = (float)(1.0 / vol);
        double id = 1.0 / det;
        g_inv[t][0] = (float)(A * id);
        g_inv[t][1] = (float)((cc * h - b * i) * id);
        g_inv[t][2] = (float)((b * f - cc * e) * id);
        g_inv[t][3] = (float)(Bv * id);
        g_inv[t][4] = (float)((a * i - cc * g) * id);
        g_inv[t][5] = (float)((cc * d - a * f) * id);
        g_inv[t][6] = (float)(C * id);
        g_inv[t][7] = (float)((b * g - a * h) * id);
        g_inv[t][8] = (float)((a * e - b * d) * id);
    }
    if (t <= NB) {   // lower_bound(batch, t) — batch is sorted
        int lo = 0, hi = NN;
        while (lo < hi) {
            int mid = (lo + hi) >> 1;
            if (batch[mid] < t) lo = mid + 1; else hi = mid;
        }
        g_off[t] = lo;
    }
}

// ---------------------------------------------------------------------------
// Kernel 1: per-atom unit phasors e^{i*2pi*frac_d*m}, m=-4..4, d=0..2.
// Only 3 sincos per atom; powers built by complex multiplication.
// Also zero-initializes the (poisoned) output buffer.
// ---------------------------------------------------------------------------
__global__ void k_phasors(const float* __restrict__ pos, const int* __restrict__ batch,
                          float* __restrict__ out)
{
    int n = blockIdx.x * blockDim.x + threadIdx.x;
    if (n >= NN) return;
    out[n] = 0.0f;
    int b = batch[n];
    float px = pos[3 * n], py = pos[3 * n + 1], pz = pos[3 * n + 2];
    #pragma unroll
    for (int d = 0; d < 3; d++) {
        // frac[d] = sum_i pos[i] * inv[i][d]
        float fr = px * g_inv[b][d] + py * g_inv[b][3 + d] + pz * g_inv[b][6 + d];
        float th = TWO_PI * fr;
        float s, c;
        sincosf(th, &s, &c);
        float re[9], im[9];
        re[4] = 1.0f; im[4] = 0.0f;
        re[5] = c;    im[5] = s;
        #pragma unroll
        for (int m = 2; m <= 4; m++) {
            re[4 + m] = re[3 + m] * c - im[3 + m] * s;
            im[4 + m] = re[3 + m] * s + im[3 + m] * c;
        }
        #pragma unroll
        for (int m = 1; m <= 4; m++) { re[4 - m] = re[4 + m]; im[4 - m] = -im[4 + m]; }
        #pragma unroll
        for (int mi = 0; mi < 9; mi++) {
            g_phas[(d * 9 + mi) * 2 + 0][n] = re[mi];
            g_phas[(d * 9 + mi) * 2 + 1][n] = im[mi];
        }
    }
}

// ---------------------------------------------------------------------------
// Kernel 2: MLP radial filter -> g_w[b][k].  One thread per (b,k).
// W2 staged transposed in shared so the inner dot is contiguous.
// ---------------------------------------------------------------------------
__global__ void __launch_bounds__(128) k_weights(
    const float* __restrict__ W1, const float* __restrict__ B1,
    const float* __restrict__ W2, const float* __restrict__ B2,
    const float* __restrict__ W3, const float* __restrict__ B3)
{
    __shared__ float sW1[3 * NH], sB1[NH], sW2T[NH * NH], sB2[NH], sW3[NH];
    __shared__ float sInv[NB * 9];
    int tid = threadIdx.x;
    for (int idx = tid; idx < 3 * NH; idx += blockDim.x) sW1[idx] = W1[idx];
    for (int idx = tid; idx < NH; idx += blockDim.x) {
        sB1[idx] = B1[idx]; sB2[idx] = B2[idx]; sW3[idx] = W3[idx];
    }
    for (int idx = tid; idx < NH * NH; idx += blockDim.x) {
        int i = idx >> 6, j = idx & 63;
        sW2T[j * NH + i] = W2[idx];
    }
    for (int idx = tid; idx < NB * 9; idx += blockDim.x)
        sInv[idx] = (&g_inv[0][0])[idx];
    __syncthreads();

    int g = blockIdx.x * blockDim.x + tid;
    if (g >= NB * NK) return;
    int b = g / NK, k = g - b * NK;
    int ki = k / 81 - 4;
    int kj = (k / 9) % 9 - 4;
    int kk = k % 9 - 4;
    const float* iv = &sInv[b * 9];
    // k_cart[h] = 2pi * sum_d klat[d] * inv[d][h]
    float kc0 = TWO_PI * ((float)ki * iv[0] + (float)kj * iv[3] + (float)kk * iv[6]);
    float kc1 = TWO_PI * ((float)ki * iv[1] + (float)kj * iv[4] + (float)kk * iv[7]);
    float kc2 = TWO_PI * ((float)ki * iv[2] + (float)kj * iv[5] + (float)kk * iv[8]);
    float kn = sqrtf(kc0 * kc0 + kc1 * kc1 + kc2 * kc2);

    float w = 0.0f;
    if (kn > 1e-6f) {           // only k=0 fails this
        float x0 = log1pf(kn);
        float f0 = x0, f1 = x0 * x0, f2 = 1.0f / kn;
        float h1[NH];
        #pragma unroll
        for (int j = 0; j < NH; j++) {
            float a = fmaf(f0, sW1[j], fmaf(f1, sW1[NH + j], fmaf(f2, sW1[2 * NH + j], sB1[j])));
            h1[j] = a / (1.0f + __expf(-a));          // silu
        }
        float o = B3[0];
        for (int j = 0; j < NH; j++) {
            float a = sB2[j];
            #pragma unroll
            for (int i2 = 0; i2 < NH; i2++) a = fmaf(h1[i2], sW2T[j * NH + i2], a);
            float h2 = a / (1.0f + __expf(-a));        // silu
            o = fmaf(h2, sW3[j], o);
        }
        float sp = (o > 80.0f) ? o : log1pf(__expf(o));  // softplus
        w = (FOUR_PI / (kn * kn)) * sp;
    }
    g_w[b][k] = w;
}

// ---------------------------------------------------------------------------
// Kernel 3 (fused): warp owns (graph b, line (i,j)) -> 9 k's.
// Pass 1: accumulate S_cos/S_sin[9][4] over the graph's atoms (lane-strided),
//         butterfly reduce so every lane holds the totals.
// Pass 2: re-walk atoms (L1-hot), compute the 9-k energy contribution per atom,
//         atomicAdd into out[n].
// ---------------------------------------------------------------------------
__global__ void __launch_bounds__(256) k_main(const float* __restrict__ source,
                                              float* __restrict__ out)
{
    int b    = blockIdx.x;
    int warp = threadIdx.x >> 5;
    int lane = threadIdx.x & 31;
    int line = blockIdx.y * 8 + warp;       // (i,j) line index, 0..80
    if (line >= 81) return;
    int i4 = line / 9, j4 = line % 9;
    int start = g_off[b], end = g_off[b + 1];

    const float* Pxr = g_phas[i4 * 2];
    const float* Pxi = g_phas[i4 * 2 + 1];
    const float* Pyr = g_phas[(9 + j4) * 2];
    const float* Pyi = g_phas[(9 + j4) * 2 + 1];

    float aC[9][4], aS[9][4];
    #pragma unroll
    for (int z = 0; z < 9; z++)
        #pragma unroll
        for (int c = 0; c < 4; c++) { aC[z][c] = 0.0f; aS[z][c] = 0.0f; }

    // ---- pass 1: structure factors for this line ----
    for (int a = start + lane; a < end; a += 32) {
        float cxr = Pxr[a], cxi = Pxi[a];
        float cyr = Pyr[a], cyi = Pyi[a];
        float c1r = cxr * cyr - cxi * cyi;
        float c1i = cxr * cyi + cxi * cyr;
        float4 sv = *(const float4*)(source + 4 * a);
        #pragma unroll
        for (int z = 0; z < 9; z++) {
            float zr = g_phas[(18 + z) * 2][a];
            float zi = g_phas[(18 + z) * 2 + 1][a];
            float cr = c1r * zr - c1i * zi;   // cos(2pi f.k)
            float ci = c1r * zi + c1i * zr;   // sin(2pi f.k)
            aC[z][0] = fmaf(sv.x, cr, aC[z][0]);
            aC[z][1] = fmaf(sv.y, cr, aC[z][1]);
            aC[z][2] = fmaf(sv.z, cr, aC[z][2]);
            aC[z][3] = fmaf(sv.w, cr, aC[z][3]);
            aS[z][0] = fmaf(sv.x, ci, aS[z][0]);
            aS[z][1] = fmaf(sv.y, ci, aS[z][1]);
            aS[z][2] = fmaf(sv.z, ci, aS[z][2]);
            aS[z][3] = fmaf(sv.w, ci, aS[z][3]);
        }
    }
    // butterfly reduce: every lane ends with the full sums
    #pragma unroll
    for (int z = 0; z < 9; z++)
        #pragma unroll
        for (int c = 0; c < 4; c++) {
            float v1 = aC[z][c], v2 = aS[z][c];
            #pragma unroll
            for (int o = 16; o; o >>= 1) {
                v1 += __shfl_xor_sync(0xffffffffu, v1, o);
                v2 += __shfl_xor_sync(0xffffffffu, v2, o);
            }
            aC[z][c] = v1; aS[z][c] = v2;
        }

    float wz[9];
    #pragma unroll
    for (int z = 0; z < 9; z++) wz[z] = g_w[b][line * 9 + z];
    float hv = 0.5f * g_vinv[b];

    // ---- pass 2: per-atom energy contribution from this line's 9 k's ----
    for (int a = start + lane; a < end; a += 32) {
        float cxr = Pxr[a], cxi = Pxi[a];
        float cyr = Pyr[a], cyi = Pyi[a];
        float c1r = cxr * cyr - cxi * cyi;
        float c1i = cxr * cyi + cxi * cyr;
        float4 sv = *(const float4*)(source + 4 * a);
        float e = 0.0f;
        #pragma unroll
        for (int z = 0; z < 9; z++) {
            float zr = g_phas[(18 + z) * 2][a];
            float zi = g_phas[(18 + z) * 2 + 1][a];
            float cr = c1r * zr - c1i * zi;
            float ci = c1r * zi + c1i * zr;
            float sc = sv.x * aC[z][0] + sv.y * aC[z][1] + sv.z * aC[z][2] + sv.w * aC[z][3];
            float ss = sv.x * aS[z][0] + sv.y * aS[z][1] + sv.z * aS[z][2] + sv.w * aS[z][3];
            e = fmaf(wz[z], fmaf(cr, sc, ci * ss), e);
        }
        atomicAdd(out + a, hv * e);
    }
}

// ---------------------------------------------------------------------------
extern "C" void kernel_launch(void* const* d_in, const int* in_sizes, int n_in,
                              void* d_out, int out_size)
{
    const float* pos    = (const float*)d_in[0];
    const int*   batch  = (const int*)d_in[1];
    const float* cell   = (const float*)d_in[2];
    const float* source = (const float*)d_in[3];
    const float* W1 = (const float*)d_in[4];
    const float* B1 = (const float*)d_in[5];
    const float* W2 = (const float*)d_in[6];
    const float* B2 = (const float*)d_in[7];
    const float* W3 = (const float*)d_in[8];
    const float* B3 = (const float*)d_in[9];
    float* out = (float*)d_out;

    k_setup  <<<1, 64>>>(cell, batch);
    k_phasors<<<(NN + 255) / 256, 256>>>(pos, batch, out);
    k_weights<<<(NB * NK + 127) / 128, 128>>>(W1, B1, W2, B2, W3, B3);
    k_main   <<<dim3(NB, 11), 256>>>(source, out);
}

// round 8
// speedup vs baseline: 1.4938x; 1.4938x over previous
#include <cuda_runtime.h>
#include <math.h>

// Problem constants (fixed by the dataset)
#define NN 8192          // atoms
#define NB 32            // graphs
#define NH 64            // hidden
#define NK 729           // 9^3 lattice points

#define TWO_PI  6.28318530717958647692f
#define FOUR_PI 12.5663706143591729539f

// half-space: lines 40..80  (i>0, or i==0 && j>0, plus the (0,0,*) line masked)
#define NLINES   41
#define NW_ITEMS (NB * NLINES * 9)          // 11808
#define PBLOCKS  (NN / 128)                 // 64 phasor blocks
#define WBLOCKS  ((NW_ITEMS + 127) / 128)   // 93 MLP blocks

// -------- device scratch (no allocations allowed) --------
__device__ float  g_vinv[NB];         // 1 / max(|det|,1e-6)
__device__ int    g_off[NB + 1];      // batch segment offsets (batch sorted)
__device__ float  g_w[NB][NK];        // radial weights (half-space entries used)
__device__ float2 g_phas2[27][NN];    // per-atom unit phasors e^{i 2pi f_d m},
                                      // row = d*9 + (m+4), col = atom (coalesced)

// ---------------------------------------------------------------------------
// 3x3 inverse in double precision -> 9 floats. Returns det (double).
// ---------------------------------------------------------------------------
__device__ __forceinline__ double inv3x3(const float* c, float* o)
{
    double a = c[0], b = c[1], cc = c[2];
    double d = c[3], e = c[4], f  = c[5];
    double g = c[6], h = c[7], i  = c[8];
    double A  = e * i - f * h;
    double Bv = f * g - d * i;
    double C  = d * h - e * g;
    double det = a * A + b * Bv + cc * C;
    double id = 1.0 / det;
    o[0] = (float)(A * id);
    o[1] = (float)((cc * h - b * i) * id);
    o[2] = (float)((b * f - cc * e) * id);
    o[3] = (float)(Bv * id);
    o[4] = (float)((a * i - cc * g) * id);
    o[5] = (float)((cc * d - a * f) * id);
    o[6] = (float)(C * id);
    o[7] = (float)((b * g - a * h) * id);
    o[8] = (float)((a * e - b * d) * id);
    return det;
}

// ---------------------------------------------------------------------------
// Fused prep kernel: blocks [0,64) do phasors + offsets + out-zero,
// blocks [64,157) do the half-space MLP radial filter.
// Every block computes the 32 cell inverses locally (cheap, deterministic).
// ---------------------------------------------------------------------------
__global__ void __launch_bounds__(128) k_prep(
    const float* __restrict__ pos, const int* __restrict__ batch,
    const float* __restrict__ cell, const float* __restrict__ source,
    const float* __restrict__ W1, const float* __restrict__ B1,
    const float* __restrict__ W2, const float* __restrict__ B2,
    const float* __restrict__ W3, const float* __restrict__ B3,
    float* __restrict__ out)
{
    __shared__ float sInv[NB * 9];
    __shared__ __align__(16) float sW2T[NH * NH];
    __shared__ float sW1[3 * NH], sB1[NH], sB2[NH], sW3[NH];

    int tid = threadIdx.x;

    // per-block cell inverses (threads 0..31)
    if (tid < NB) {
        double det = inv3x3(cell + tid * 9, &sInv[tid * 9]);
        if (blockIdx.x == 0) {
            double vol = fabs(det);
            if (vol < 1e-6) vol = 1e-6;
            g_vinv[tid] = (float)(1.0 / vol);
        }
    }
    __syncthreads();

    if (blockIdx.x < PBLOCKS) {
        // ---------------- phasor role ----------------
        int n = blockIdx.x * 128 + tid;
        out[n] = 0.0f;

        int b = batch[n];
        // parallel segment-offset scan (batch is sorted)
        if (n == 0) {
            g_off[0] = 0;
            for (int bb = 1; bb <= b; bb++) g_off[bb] = 0;
        }
        if (n == NN - 1) {
            for (int bb = b + 1; bb <= NB; bb++) g_off[bb] = NN;
        } else {
            int b2 = batch[n + 1];
            for (int bb = b + 1; bb <= b2; bb++) g_off[bb] = n + 1;
        }

        float px = pos[3 * n], py = pos[3 * n + 1], pz = pos[3 * n + 2];
        const float* iv = &sInv[b * 9];
        #pragma unroll
        for (int d = 0; d < 3; d++) {
            float fr = px * iv[d] + py * iv[3 + d] + pz * iv[6 + d];
            float s, c;
            sincosf(TWO_PI * fr, &s, &c);
            float re[9], im[9];
            re[4] = 1.0f; im[4] = 0.0f;
            re[5] = c;    im[5] = s;
            #pragma unroll
            for (int m = 2; m <= 4; m++) {
                re[4 + m] = re[3 + m] * c - im[3 + m] * s;
                im[4 + m] = re[3 + m] * s + im[3 + m] * c;
            }
            #pragma unroll
            for (int m = 1; m <= 4; m++) { re[4 - m] = re[4 + m]; im[4 - m] = -im[4 + m]; }
            #pragma unroll
            for (int mi = 0; mi < 9; mi++) {
                float2 v; v.x = re[mi]; v.y = im[mi];
                g_phas2[d * 9 + mi][n] = v;
            }
        }
    } else {
        // ---------------- MLP weight role (half-space only) ----------------
        for (int idx = tid; idx < 3 * NH; idx += 128) sW1[idx] = W1[idx];
        for (int idx = tid; idx < NH; idx += 128) {
            sB1[idx] = B1[idx]; sB2[idx] = B2[idx]; sW3[idx] = W3[idx];
        }
        for (int idx = tid; idx < NH * NH; idx += 128) {
            int i = idx >> 6, j = idx & 63;
            sW2T[j * NH + i] = W2[idx];
        }
        __syncthreads();

        int g = (blockIdx.x - PBLOCKS) * 128 + tid;
        if (g >= NW_ITEMS) return;
        int b    = g / (NLINES * 9);
        int rem  = g - b * (NLINES * 9);
        int line = 40 + rem / 9;
        int z    = rem % 9;
        int ki = line / 9 - 4;
        int kj = line % 9 - 4;
        int kk = z - 4;
        const float* iv = &sInv[b * 9];
        float kc0 = TWO_PI * ((float)ki * iv[0] + (float)kj * iv[3] + (float)kk * iv[6]);
        float kc1 = TWO_PI * ((float)ki * iv[1] + (float)kj * iv[4] + (float)kk * iv[7]);
        float kc2 = TWO_PI * ((float)ki * iv[2] + (float)kj * iv[5] + (float)kk * iv[8]);
        float kn = sqrtf(kc0 * kc0 + kc1 * kc1 + kc2 * kc2);

        float w = 0.0f;
        // (0,0,m<=0) entries are outside the half-space -> w = 0
        bool active = (kn > 1e-6f) && !(line == 40 && z < 4);
        if (active) {
            float x0 = log1pf(kn);
            float f0 = x0, f1 = x0 * x0, f2 = 1.0f / kn;
            float h1[NH];
            #pragma unroll
            for (int j = 0; j < NH; j++) {
                float a = fmaf(f0, sW1[j], fmaf(f1, sW1[NH + j], fmaf(f2, sW1[2 * NH + j], sB1[j])));
                h1[j] = a / (1.0f + __expf(-a));             // silu
            }
            float o = B3[0];
            for (int j = 0; j < NH; j++) {
                float a = sB2[j];
                const float4* wrow = (const float4*)&sW2T[j * NH];
                #pragma unroll
                for (int i2 = 0; i2 < NH / 4; i2++) {
                    float4 wv = wrow[i2];
                    a = fmaf(h1[4 * i2 + 0], wv.x,
                        fmaf(h1[4 * i2 + 1], wv.y,
                        fmaf(h1[4 * i2 + 2], wv.z,
                        fmaf(h1[4 * i2 + 3], wv.w, a))));
                }
                float h2 = a / (1.0f + __expf(-a));           // silu
                o = fmaf(h2, sW3[j], o);
            }
            float sp = (o > 80.0f) ? o : log1pf(__expf(o));   // softplus
            w = (FOUR_PI / (kn * kn)) * sp;
        }
        g_w[b][line * 9 + z] = w;
    }
}

// ---------------------------------------------------------------------------
// Fused main kernel: one 32-thread block per (graph b, half-space line).
// Pass 1: accumulate S_cos/S_sin[9][4] over the graph's atoms; butterfly
//         reduce so every lane holds the totals.
// Pass 2: re-walk the atoms (L1-hot), per-atom 9-k energy, red.global.add.
// z phasors come from a 2-value recurrence (z^-4 start, z^+1 step) instead of
// 18 global loads per atom.
// Half-space symmetry contributes a factor 2, which cancels the 0.5.
// ---------------------------------------------------------------------------
__global__ void __launch_bounds__(32) k_main(const float* __restrict__ source,
                                             float* __restrict__ out)
{
    int b    = blockIdx.x;
    int line = 40 + blockIdx.y;           // 40..80
    int lane = threadIdx.x;
    int i4 = line / 9, j4 = line % 9;
    int start = g_off[b], end = g_off[b + 1];

    const float2* __restrict__ PX  = g_phas2[i4];
    const float2* __restrict__ PY  = g_phas2[9 + j4];
    const float2* __restrict__ PZ0 = g_phas2[18];      // m_z = -4
    const float2* __restrict__ PZS = g_phas2[23];      // m_z = +1
    const float4* __restrict__ SRC = (const float4*)source;

    float aC[9][4], aS[9][4];
    #pragma unroll
    for (int z = 0; z < 9; z++)
        #pragma unroll
        for (int c = 0; c < 4; c++) { aC[z][c] = 0.0f; aS[z][c] = 0.0f; }

    // ---- pass 1: structure factors (prefetched) ----
    {
        int a = start + lane;
        float2 LX, LY, LZ0, LZS; float4 LSV;
        if (a < end) { LX = PX[a]; LY = PY[a]; LZ0 = PZ0[a]; LZS = PZS[a]; LSV = SRC[a]; }
        while (a < end) {
            float2 X = LX, Y = LY, Z0 = LZ0, ZS = LZS; float4 sv = LSV;
            int an = a + 32;
            if (an < end) { LX = PX[an]; LY = PY[an]; LZ0 = PZ0[an]; LZS = PZS[an]; LSV = SRC[an]; }
            float c1r = X.x * Y.x - X.y * Y.y;
            float c1i = X.x * Y.y + X.y * Y.x;
            float cr = c1r * Z0.x - c1i * Z0.y;
            float ci = c1r * Z0.y + c1i * Z0.x;
            #pragma unroll
            for (int z = 0; z < 9; z++) {
                aC[z][0] = fmaf(sv.x, cr, aC[z][0]);
                aC[z][1] = fmaf(sv.y, cr, aC[z][1]);
                aC[z][2] = fmaf(sv.z, cr, aC[z][2]);
                aC[z][3] = fmaf(sv.w, cr, aC[z][3]);
                aS[z][0] = fmaf(sv.x, ci, aS[z][0]);
                aS[z][1] = fmaf(sv.y, ci, aS[z][1]);
                aS[z][2] = fmaf(sv.z, ci, aS[z][2]);
                aS[z][3] = fmaf(sv.w, ci, aS[z][3]);
                if (z < 8) {
                    float t = cr * ZS.x - ci * ZS.y;
                    ci      = cr * ZS.y + ci * ZS.x;
                    cr      = t;
                }
            }
            a = an;
        }
    }

    // butterfly reduce: every lane ends with the full sums
    #pragma unroll
    for (int z = 0; z < 9; z++)
        #pragma unroll
        for (int c = 0; c < 4; c++) {
            float v1 = aC[z][c], v2 = aS[z][c];
            #pragma unroll
            for (int o = 16; o; o >>= 1) {
                v1 += __shfl_xor_sync(0xffffffffu, v1, o);
                v2 += __shfl_xor_sync(0xffffffffu, v2, o);
            }
            aC[z][c] = v1; aS[z][c] = v2;
        }

    float wz[9];
    #pragma unroll
    for (int z = 0; z < 9; z++) wz[z] = g_w[b][line * 9 + z];
    float hv = g_vinv[b];   // 0.5 (energy) x 2 (half-space) = 1

    // ---- pass 2: per-atom energy from this line's 9 k's ----
    {
        int a = start + lane;
        float2 LX, LY, LZ0, LZS; float4 LSV;
        if (a < end) { LX = PX[a]; LY = PY[a]; LZ0 = PZ0[a]; LZS = PZS[a]; LSV = SRC[a]; }
        while (a < end) {
            float2 X = LX, Y = LY, Z0 = LZ0, ZS = LZS; float4 sv = LSV;
            int an = a + 32;
            if (an < end) { LX = PX[an]; LY = PY[an]; LZ0 = PZ0[an]; LZS = PZS[an]; LSV = SRC[an]; }
            float c1r = X.x * Y.x - X.y * Y.y;
            float c1i = X.x * Y.y + X.y * Y.x;
            float cr = c1r * Z0.x - c1i * Z0.y;
            float ci = c1r * Z0.y + c1i * Z0.x;
            float e = 0.0f;
            #pragma unroll
            for (int z = 0; z < 9; z++) {
                float sc = sv.x * aC[z][0] + sv.y * aC[z][1] + sv.z * aC[z][2] + sv.w * aC[z][3];
                float ss = sv.x * aS[z][0] + sv.y * aS[z][1] + sv.z * aS[z][2] + sv.w * aS[z][3];
                e = fmaf(wz[z], fmaf(cr, sc, ci * ss), e);
                if (z < 8) {
                    float t = cr * ZS.x - ci * ZS.y;
                    ci      = cr * ZS.y + ci * ZS.x;
                    cr      = t;
                }
            }
            atomicAdd(out + a, hv * e);
            a = an;
        }
    }
}

// ---------------------------------------------------------------------------
extern "C" void kernel_launch(void* const* d_in, const int* in_sizes, int n_in,
                              void* d_out, int out_size)
{
    const float* pos    = (const float*)d_in[0];
    const int*   batch  = (const int*)d_in[1];
    const float* cell   = (const float*)d_in[2];
    const float* source = (const float*)d_in[3];
    const float* W1 = (const float*)d_in[4];
    const float* B1 = (const float*)d_in[5];
    const float* W2 = (const float*)d_in[6];
    const float* B2 = (const float*)d_in[7];
    const float* W3 = (const float*)d_in[8];
    const float* B3 = (const float*)d_in[9];
    float* out = (float*)d_out;

    k_prep<<<PBLOCKS + WBLOCKS, 128>>>(pos, batch, cell, source,
                                       W1, B1, W2, B2, W3, B3, out);
    k_main<<<dim3(NB, NLINES), 32>>>(source, out);
}

// round 9
// speedup vs baseline: 2.0104x; 1.3458x over previous
#include <cuda_runtime.h>
#include <math.h>

// Problem constants (fixed by the dataset)
#define NN 8192          // atoms
#define NB 32            // graphs
#define NH 64            // hidden
#define NK 729           // 9^3 lattice points

#define TWO_PI  6.28318530717958647692f
#define FOUR_PI 12.5663706143591729539f

// half-space: lines 40..80 (m_i>0, or m_i==0 && m_j>0, plus (0,0,*) masked to m_z>0)
#define NLINES   41
#define NW_ITEMS (NB * NLINES * 9)          // 11808
#define WB ((NW_ITEMS + 63) / 64)           // 185 MLP blocks (launched first)
#define PB (NN / 64)                        // 128 phasor blocks

typedef unsigned long long u64;

// -------- device scratch (no allocations allowed) --------
__device__ float  g_vinv[NB];
__device__ int    g_off[NB + 1];
__device__ float  g_w[NB][NK];
__device__ float2 g_phas2[27][NN];   // unit phasors e^{i 2pi f_d m}, row-major over (d,m)

// ---------------- packed f32x2 helpers ----------------
__device__ __forceinline__ u64 pk2(float lo, float hi) {
    u64 r; asm("mov.b64 %0,{%1,%2};" : "=l"(r) : "f"(lo), "f"(hi)); return r;
}
__device__ __forceinline__ void upk2(u64 v, float& lo, float& hi) {
    asm("mov.b64 {%0,%1},%2;" : "=f"(lo), "=f"(hi) : "l"(v));
}
__device__ __forceinline__ u64 f2fma(u64 a, u64 b, u64 c) {
    u64 d; asm("fma.rn.f32x2 %0,%1,%2,%3;" : "=l"(d) : "l"(a), "l"(b), "l"(c)); return d;
}
__device__ __forceinline__ u64 f2add(u64 a, u64 b) {
    u64 d; asm("add.rn.f32x2 %0,%1,%2;" : "=l"(d) : "l"(a), "l"(b)); return d;
}
__device__ __forceinline__ u64 f2mul(u64 a, u64 b) {
    u64 d; asm("mul.rn.f32x2 %0,%1,%2;" : "=l"(d) : "l"(a), "l"(b)); return d;
}

// ---------------------------------------------------------------------------
// 3x3 inverse (double precision). Returns det.
// ---------------------------------------------------------------------------
__device__ __forceinline__ double inv3x3(const float* c, float* o)
{
    double a = c[0], b = c[1], cc = c[2];
    double d = c[3], e = c[4], f  = c[5];
    double g = c[6], h = c[7], i  = c[8];
    double A  = e * i - f * h;
    double Bv = f * g - d * i;
    double C  = d * h - e * g;
    double det = a * A + b * Bv + cc * C;
    double id = 1.0 / det;
    o[0] = (float)(A * id);
    o[1] = (float)((cc * h - b * i) * id);
    o[2] = (float)((b * f - cc * e) * id);
    o[3] = (float)(Bv * id);
    o[4] = (float)((a * i - cc * g) * id);
    o[5] = (float)((cc * d - a * f) * id);
    o[6] = (float)(C * id);
    o[7] = (float)((b * g - a * h) * id);
    o[8] = (float)((a * e - b * d) * id);
    return det;
}

// ---------------------------------------------------------------------------
// Fused prep kernel. Blocks [0,WB): MLP radial filter (half-space).
// Blocks [WB,WB+PB): per-atom phasors + batch offsets + out-zero.
// ---------------------------------------------------------------------------
__global__ void __launch_bounds__(64) k_prep(
    const float* __restrict__ pos, const int* __restrict__ batch,
    const float* __restrict__ cell,
    const float* __restrict__ W1, const float* __restrict__ B1,
    const float* __restrict__ W2, const float* __restrict__ B2,
    const float* __restrict__ W3, const float* __restrict__ B3,
    float* __restrict__ out)
{
    __shared__ float sInv[NB * 9];
    __shared__ __align__(16) float sW2T[NH * 72];   // row j padded to 72 floats
    __shared__ float sW1[3 * NH], sB1[NH], sB2[NH], sW3[NH];

    int tid = threadIdx.x;

    if (tid < NB) {
        double det = inv3x3(cell + tid * 9, &sInv[tid * 9]);
        if (blockIdx.x == 0) {
            double vol = fabs(det);
            if (vol < 1e-6) vol = 1e-6;
            g_vinv[tid] = (float)(1.0 / vol);
        }
    }

    if (blockIdx.x < WB) {
        // ---------------- MLP role ----------------
        for (int idx = tid; idx < 3 * NH; idx += 64) sW1[idx] = W1[idx];
        for (int idx = tid; idx < NH; idx += 64) {
            sB1[idx] = B1[idx]; sB2[idx] = B2[idx]; sW3[idx] = W3[idx];
        }
        for (int idx = tid; idx < NH * NH; idx += 64) {
            int i = idx >> 6, j = idx & 63;
            sW2T[j * 72 + i] = W2[idx];
        }
        __syncthreads();

        int g = blockIdx.x * 64 + tid;
        if (g >= NW_ITEMS) return;
        int b    = g / (NLINES * 9);
        int rem  = g - b * (NLINES * 9);
        int line = 40 + rem / 9;
        int z    = rem % 9;
        int ki = line / 9 - 4;
        int kj = line % 9 - 4;
        int kk = z - 4;
        const float* iv = &sInv[b * 9];
        float kc0 = TWO_PI * ((float)ki * iv[0] + (float)kj * iv[3] + (float)kk * iv[6]);
        float kc1 = TWO_PI * ((float)ki * iv[1] + (float)kj * iv[4] + (float)kk * iv[7]);
        float kc2 = TWO_PI * ((float)ki * iv[2] + (float)kj * iv[5] + (float)kk * iv[8]);
        float kn = sqrtf(kc0 * kc0 + kc1 * kc1 + kc2 * kc2);

        float w = 0.0f;
        bool active = (kn > 1e-6f) && !(line == 40 && z < 4);   // half-space mask
        if (active) {
            float x0 = log1pf(kn);
            float f0 = x0, f1 = x0 * x0, f2 = 1.0f / kn;
            u64 h1p[NH / 2];
            #pragma unroll
            for (int j = 0; j < NH; j += 2) {
                float a0 = fmaf(f0, sW1[j],     fmaf(f1, sW1[NH + j],     fmaf(f2, sW1[2 * NH + j],     sB1[j])));
                float a1 = fmaf(f0, sW1[j + 1], fmaf(f1, sW1[NH + j + 1], fmaf(f2, sW1[2 * NH + j + 1], sB1[j + 1])));
                float h0 = __fdividef(a0, 1.0f + __expf(-a0));   // silu
                float h1 = __fdividef(a1, 1.0f + __expf(-a1));
                h1p[j >> 1] = pk2(h0, h1);
            }
            float o = B3[0];
            for (int j = 0; j < NH; j++) {
                const ulonglong2* wr = (const ulonglong2*)&sW2T[j * 72];
                u64 acc0 = pk2(sB2[j], 0.0f);
                u64 acc1 = 0ULL;
                #pragma unroll
                for (int i2 = 0; i2 < 16; i2++) {
                    ulonglong2 wv = wr[i2];
                    acc0 = f2fma(h1p[2 * i2],     wv.x, acc0);
                    acc1 = f2fma(h1p[2 * i2 + 1], wv.y, acc1);
                }
                float p0, p1, q0, q1;
                upk2(acc0, p0, p1); upk2(acc1, q0, q1);
                float a = (p0 + p1) + (q0 + q1);
                float h2 = __fdividef(a, 1.0f + __expf(-a));     // silu
                o = fmaf(h2, sW3[j], o);
            }
            float sp = (o > 80.0f) ? o : log1pf(__expf(o));       // softplus
            w = (FOUR_PI / (kn * kn)) * sp;
        }
        g_w[b][line * 9 + z] = w;
    } else {
        // ---------------- phasor role ----------------
        __syncthreads();
        int n = (blockIdx.x - WB) * 64 + tid;
        out[n] = 0.0f;

        int b = batch[n];
        if (n == 0) {
            g_off[0] = 0;
            for (int bb = 1; bb <= b; bb++) g_off[bb] = 0;
        }
        if (n == NN - 1) {
            for (int bb = b + 1; bb <= NB; bb++) g_off[bb] = NN;
        } else {
            int b2 = batch[n + 1];
            for (int bb = b + 1; bb <= b2; bb++) g_off[bb] = n + 1;
        }

        float px = pos[3 * n], py = pos[3 * n + 1], pz = pos[3 * n + 2];
        const float* iv = &sInv[b * 9];
        #pragma unroll
        for (int d = 0; d < 3; d++) {
            float fr = px * iv[d] + py * iv[3 + d] + pz * iv[6 + d];
            float s, c;
            sincosf(TWO_PI * fr, &s, &c);
            float re[9], im[9];
            re[4] = 1.0f; im[4] = 0.0f;
            re[5] = c;    im[5] = s;
            #pragma unroll
            for (int m = 2; m <= 4; m++) {
                re[4 + m] = re[3 + m] * c - im[3 + m] * s;
                im[4 + m] = re[3 + m] * s + im[3 + m] * c;
            }
            #pragma unroll
            for (int m = 1; m <= 4; m++) { re[4 - m] = re[4 + m]; im[4 - m] = -im[4 + m]; }
            #pragma unroll
            for (int mi = 0; mi < 9; mi++) {
                float2 v; v.x = re[mi]; v.y = im[mi];
                g_phas2[d * 9 + mi][n] = v;
            }
        }
    }
}

// ---------------------------------------------------------------------------
// Fused main kernel: 64-thread block per (graph b, half-space line).
// Two warps split the atom range. Packed f32x2 accumulators (SC,SS) per
// (z, channel). Cross-lane reduction = distributed exchange (lane l ends
// owning value l) + 4-value butterfly tail + one smem round-trip that also
// combines the two warps. Factor 2 (half-space) cancels the 0.5.
// ---------------------------------------------------------------------------
__global__ void __launch_bounds__(64) k_main(const float* __restrict__ source,
                                             float* __restrict__ out)
{
    __shared__ u64 sS[2][36];

    int b    = blockIdx.x;
    int line = 40 + blockIdx.y;
    int w    = threadIdx.x >> 5;
    int lane = threadIdx.x & 31;
    int i4 = line / 9, j4 = line % 9;
    int start = g_off[b], end = g_off[b + 1];

    const float2* __restrict__ PX  = g_phas2[i4];
    const float2* __restrict__ PY  = g_phas2[9 + j4];
    const float2* __restrict__ PZ0 = g_phas2[18];      // m_z = -4
    const float2* __restrict__ PZS = g_phas2[23];      // m_z = +1
    const float4* __restrict__ SRC = (const float4*)source;

    u64 acc[36];            // packed (SC, SS) partials, index v = z*4 + c
    #pragma unroll
    for (int v = 0; v < 36; v++) acc[v] = 0ULL;

    // ---- pass 1: structure factors (this warp's atom share) ----
    {
        int a = start + lane + 32 * w;
        float2 LX, LY, LZ0, LZS; float4 LSV;
        if (a < end) { LX = PX[a]; LY = PY[a]; LZ0 = PZ0[a]; LZS = PZS[a]; LSV = SRC[a]; }
        while (a < end) {
            float2 X = LX, Y = LY, Z0 = LZ0, ZS = LZS; float4 sv = LSV;
            int an = a + 64;
            if (an < end) { LX = PX[an]; LY = PY[an]; LZ0 = PZ0[an]; LZS = PZS[an]; LSV = SRC[an]; }
            float c1r = X.x * Y.x - X.y * Y.y;
            float c1i = X.x * Y.y + X.y * Y.x;
            float cr = c1r * Z0.x - c1i * Z0.y;
            float ci = c1r * Z0.y + c1i * Z0.x;
            u64 p  = pk2(cr, ci);
            u64 s0 = pk2(sv.x, sv.x), s1 = pk2(sv.y, sv.y);
            u64 s2 = pk2(sv.z, sv.z), s3 = pk2(sv.w, sv.w);
            #pragma unroll
            for (int z = 0; z < 9; z++) {
                acc[z * 4 + 0] = f2fma(s0, p, acc[z * 4 + 0]);
                acc[z * 4 + 1] = f2fma(s1, p, acc[z * 4 + 1]);
                acc[z * 4 + 2] = f2fma(s2, p, acc[z * 4 + 2]);
                acc[z * 4 + 3] = f2fma(s3, p, acc[z * 4 + 3]);
                if (z < 8) {
                    float t = cr * ZS.x - ci * ZS.y;
                    ci = fmaf(cr, ZS.y, ci * ZS.x);
                    cr = t;
                    p = pk2(cr, ci);
                }
            }
            a = an;
        }
    }

    // ---- distributed exchange reduce on acc[0..31]: lane l ends with value l ----
    #pragma unroll
    for (int o = 16; o >= 1; o >>= 1) {
        bool hi = (lane & o) != 0;
        #pragma unroll
        for (int j = 0; j < o; j++) {
            u64 tlo = __shfl_xor_sync(0xffffffffu, acc[j],     o);
            u64 thi = __shfl_xor_sync(0xffffffffu, acc[j + o], o);
            acc[j] = hi ? f2add(acc[j + o], thi) : f2add(acc[j], tlo);
        }
    }
    sS[w][lane] = acc[0];
    // tail values 32..35 (z=8): full butterfly, all lanes end with totals
    #pragma unroll
    for (int o = 16; o; o >>= 1) {
        acc[32] = f2add(acc[32], __shfl_xor_sync(0xffffffffu, acc[32], o));
        acc[33] = f2add(acc[33], __shfl_xor_sync(0xffffffffu, acc[33], o));
        acc[34] = f2add(acc[34], __shfl_xor_sync(0xffffffffu, acc[34], o));
        acc[35] = f2add(acc[35], __shfl_xor_sync(0xffffffffu, acc[35], o));
    }
    if (lane < 4) {
        u64 qv = (lane == 0) ? acc[32] : (lane == 1) ? acc[33] : (lane == 2) ? acc[34] : acc[35];
        sS[w][32 + lane] = qv;
    }
    __syncthreads();

    // ---- combine the two warps + fold in w(k): Wp[v] = wz * (S0[v] + S1[v]) ----
    u64 Wp[36];
    #pragma unroll
    for (int z = 0; z < 9; z++) {
        float wzv = g_w[b][line * 9 + z];
        u64 wzp = pk2(wzv, wzv);
        #pragma unroll
        for (int c = 0; c < 4; c++) {
            int v = z * 4 + c;
            Wp[v] = f2mul(wzp, f2add(sS[0][v], sS[1][v]));
        }
    }
    float hv = g_vinv[b];   // 0.5 (energy) x 2 (half-space) = 1

    // ---- pass 2: per-atom energy from this line's 9 k's ----
    {
        int a = start + lane + 32 * w;
        float2 LX, LY, LZ0, LZS; float4 LSV;
        if (a < end) { LX = PX[a]; LY = PY[a]; LZ0 = PZ0[a]; LZS = PZS[a]; LSV = SRC[a]; }
        while (a < end) {
            float2 X = LX, Y = LY, Z0 = LZ0, ZS = LZS; float4 sv = LSV;
            int an = a + 64;
            if (an < end) { LX = PX[an]; LY = PY[an]; LZ0 = PZ0[an]; LZS = PZS[an]; LSV = SRC[an]; }
            float c1r = X.x * Y.x - X.y * Y.y;
            float c1i = X.x * Y.y + X.y * Y.x;
            float cr = c1r * Z0.x - c1i * Z0.y;
            float ci = c1r * Z0.y + c1i * Z0.x;
            u64 p = pk2(cr, ci);
            u64 E0 = 0ULL, E1 = 0ULL, E2 = 0ULL, E3 = 0ULL;
            #pragma unroll
            for (int z = 0; z < 9; z++) {
                E0 = f2fma(p, Wp[z * 4 + 0], E0);
                E1 = f2fma(p, Wp[z * 4 + 1], E1);
                E2 = f2fma(p, Wp[z * 4 + 2], E2);
                E3 = f2fma(p, Wp[z * 4 + 3], E3);
                if (z < 8) {
                    float t = cr * ZS.x - ci * ZS.y;
                    ci = fmaf(cr, ZS.y, ci * ZS.x);
                    cr = t;
                    p = pk2(cr, ci);
                }
            }
            float e0a, e0b, e1a, e1b, e2a, e2b, e3a, e3b;
            upk2(E0, e0a, e0b); upk2(E1, e1a, e1b);
            upk2(E2, e2a, e2b); upk2(E3, e3a, e3b);
            float e = sv.x * (e0a + e0b) + sv.y * (e1a + e1b)
                    + sv.z * (e2a + e2b) + sv.w * (e3a + e3b);
            atomicAdd(out + a, hv * e);
            a = an;
        }
    }
}

// ---------------------------------------------------------------------------
extern "C" void kernel_launch(void* const* d_in, const int* in_sizes, int n_in,
                              void* d_out, int out_size)
{
    const float* pos    = (const float*)d_in[0];
    const int*   batch  = (const int*)d_in[1];
    const float* cell   = (const float*)d_in[2];
    const float* source = (const float*)d_in[3];
    const float* W1 = (const float*)d_in[4];
    const float* B1 = (const float*)d_in[5];
    const float* W2 = (const float*)d_in[6];
    const float* B2 = (const float*)d_in[7];
    const float* W3 = (const float*)d_in[8];
    const float* B3 = (const float*)d_in[9];
    float* out = (float*)d_out;

    k_prep<<<WB + PB, 64>>>(pos, batch, cell, W1, B1, W2, B2, W3, B3, out);
    k_main<<<dim3(NB, NLINES), 64>>>(source, out);
}